// round 3
// baseline (speedup 1.0000x reference)
#include <cuda_runtime.h>

// ---------------------------------------------------------------------------
// GNNEncoder: 2-layer GCN. out[d] = dinv[d]*sum_{(s,d)}(x[s]@W)*dinv[s] + b
// edge_index dtype is detected at runtime (int32 vs int64 viewed as int32
// pairs) — JAX downcasts int64->int32 unless x64 is enabled, and reading the
// buffer as int64 overruns it 2x (the round-1/2 crashes).
// All scratch in __device__ globals; graph-capturable (kernel launches only).
// ---------------------------------------------------------------------------

#define NODES_MAX 50000
#define EDGES_MAX 800000
#define NPART     1024

__device__ int   g_odd_or;                 // !=0  =>  edge_index is int32
__device__ int   g_cnt[NODES_MAX];
__device__ int   g_off[NODES_MAX + 1];
__device__ int   g_cursor[NODES_MAX];
__device__ int   g_csr_src[EDGES_MAX];
__device__ int   g_part[NPART];
__device__ float g_dinv[NODES_MAX];
__device__ float g_hs [NODES_MAX * 128];   // layer1 (x@W1)*dinv
__device__ float g_x2 [NODES_MAX * 128];   // layer1 output (post relu)
__device__ float g_hs2[NODES_MAX * 64];    // layer2 (x2@W2)*dinv

__global__ void k_zero(int n)
{
    int i = blockIdx.x * blockDim.x + threadIdx.x;
    if (i < n) g_cnt[i] = 0;
    if (i == 0) g_odd_or = 0;
}

// Detect dtype: int64 data viewed as int32 has all odd words == 0
// (values are in [0, 50000)). 256 odd words checked — indices < 512,
// safely inside the buffer for either dtype.
__global__ void k_detect(const int* __restrict__ v)
{
    int x = v[2 * threadIdx.x + 1];
    if (x != 0) atomicOr(&g_odd_or, 1);
}

__global__ void k_hist(const int* __restrict__ v, int E, int N)
{
    int i = blockIdx.x * blockDim.x + threadIdx.x;
    if (i >= E) return;
    int is32  = g_odd_or;
    int s     = is32 ? 1 : 2;
    int dbase = is32 ? E : 2 * E;
    unsigned d = (unsigned)v[dbase + s * i];
    if (d < (unsigned)N) atomicAdd(&g_cnt[d], 1);
}

// Pass 1: 1024 partial sums over contiguous chunks of g_cnt.
__global__ void k_part(int N)
{
    int t = blockIdx.x * blockDim.x + threadIdx.x;
    if (t >= NPART) return;
    int ch  = (N + NPART - 1) / NPART;
    int beg = t * ch;
    int end = min(beg + ch, N);
    int s = 0;
    for (int i = beg; i < end; i++) s += g_cnt[i];
    g_part[t] = s;
}

// Pass 2: one warp exclusive-scans the 1024 partials (registers + shfl only).
__global__ void k_scanpart()
{
    int lane = threadIdx.x & 31;                      // <<<1,32>>>
    const int CH = NPART / 32;
    int base = lane * CH;
    int s = 0;
    for (int i = 0; i < CH; i++) s += g_part[base + i];
    int pre = s;
#pragma unroll
    for (int o = 1; o < 32; o <<= 1) {
        int vv = __shfl_up_sync(0xffffffffu, pre, o);
        if (lane >= o) pre += vv;
    }
    int run = pre - s;                                // exclusive base
    for (int i = 0; i < CH; i++) {
        int c = g_part[base + i];
        g_part[base + i] = run;
        run += c;
    }
}

// Pass 3: expand partial prefixes into per-node offsets, cursors, dinv.
__global__ void k_offsets(int N, int E)
{
    int t = blockIdx.x * blockDim.x + threadIdx.x;
    if (t >= NPART) return;
    int ch  = (N + NPART - 1) / NPART;
    int beg = t * ch;
    int end = min(beg + ch, N);
    int run = g_part[t];
    for (int i = beg; i < end; i++) {
        int c = g_cnt[i];
        g_off[i]    = run;
        g_cursor[i] = run;
        g_dinv[i]   = rsqrtf((float)(c + 1));         // +1 self loop
        run += c;
    }
    if (t == 0) g_off[N] = E;
}

__global__ void k_fill(const int* __restrict__ v, int E, int N)
{
    int i = blockIdx.x * blockDim.x + threadIdx.x;
    if (i >= E) return;
    int is32  = g_odd_or;
    int s     = is32 ? 1 : 2;
    int dbase = is32 ? E : 2 * E;
    unsigned d  = (unsigned)v[dbase + s * i];
    unsigned sr = (unsigned)v[s * i];
    if (d < (unsigned)N && sr < (unsigned)N) {
        int pos = atomicAdd(&g_cursor[d], 1);
        g_csr_src[pos] = (int)sr;
    }
}

// ---------------------------------------------------------------------------
// Shared-free GEMM: H[row] = (X[row] @ W) * dinv[row]
//   One warp computes 2 rows; lane owns DOUT/32 output columns.
//   x broadcast via shfl; W streamed via vector LDG (L1-resident, 64/32 KB).
// ---------------------------------------------------------------------------
template <int DOUT, int LAYER>
__global__ void k_gemm(const float* __restrict__ Xp,
                       const float* __restrict__ W, int N)
{
    constexpr int RPW = 2;
    constexpr int CPL = DOUT / 32;     // 4 (dout=128) or 2 (dout=64)

    const float* X = (LAYER == 0) ? Xp : g_x2;
    float*       H = (LAYER == 0) ? g_hs : g_hs2;

    int warp = (blockIdx.x * blockDim.x + threadIdx.x) >> 5;
    int lane = threadIdx.x & 31;
    int row0 = warp * RPW;
    if (row0 >= N) return;

    float acc[RPW][CPL];
#pragma unroll
    for (int r = 0; r < RPW; r++)
#pragma unroll
        for (int c = 0; c < CPL; c++) acc[r][c] = 0.f;

    for (int kb = 0; kb < 128; kb += 32) {
        float xk[RPW];
#pragma unroll
        for (int r = 0; r < RPW; r++) {
            int row = row0 + r;
            xk[r] = (row < N) ? X[row * 128 + kb + lane] : 0.f;
        }
#pragma unroll
        for (int j = 0; j < 32; j++) {
            if (CPL == 4) {
                float4 w = *(const float4*)&W[(kb + j) * DOUT + lane * 4];
#pragma unroll
                for (int r = 0; r < RPW; r++) {
                    float xv = __shfl_sync(0xffffffffu, xk[r], j);
                    acc[r][0] += xv * w.x;
                    acc[r][1] += xv * w.y;
                    acc[r][2] += xv * w.z;
                    acc[r][3] += xv * w.w;
                }
            } else {
                float2 w = *(const float2*)&W[(kb + j) * DOUT + lane * 2];
#pragma unroll
                for (int r = 0; r < RPW; r++) {
                    float xv = __shfl_sync(0xffffffffu, xk[r], j);
                    acc[r][0] += xv * w.x;
                    acc[r][1] += xv * w.y;
                }
            }
        }
    }

#pragma unroll
    for (int r = 0; r < RPW; r++) {
        int row = row0 + r;
        if (row < N) {
            float s = g_dinv[row];
            if (CPL == 4) {
                float4 o;
                o.x = acc[r][0] * s; o.y = acc[r][1] * s;
                o.z = acc[r][2] * s; o.w = acc[r][3] * s;
                *(float4*)&H[row * DOUT + lane * 4] = o;
            } else {
                float2 o;
                o.x = acc[r][0] * s; o.y = acc[r][1] * s;
                *(float2*)&H[row * DOUT + lane * 2] = o;
            }
        }
    }
}

// ---------------------------------------------------------------------------
// Aggregate per dst node: OUT[d] = dinv[d]*(HS[d] + sum_in HS[src]) + b (+relu)
// ---------------------------------------------------------------------------
template <int DOUT, bool RELU, int LAYER>
__global__ void k_agg(const float* __restrict__ bias,
                      float* __restrict__ outp, int N)
{
    constexpr int TPN = DOUT / 4;         // threads per node (float4 lanes)
    constexpr int NPB = 256 / TPN;        // nodes per block

    const float* HS  = (LAYER == 0) ? g_hs : g_hs2;
    float*       OUT = (LAYER == 0) ? g_x2 : outp;

    int t    = threadIdx.x;
    int node = blockIdx.x * NPB + t / TPN;
    int c    = (t % TPN) * 4;
    if (node >= N) return;

    float4 acc = *(const float4*)&HS[node * DOUT + c];   // self loop

    int s = g_off[node];
    int e = g_off[node + 1];
    for (int i = s; i < e; i++) {
        int src = g_csr_src[i];
        float4 v = *(const float4*)&HS[src * DOUT + c];
        acc.x += v.x; acc.y += v.y; acc.z += v.z; acc.w += v.w;
    }

    float d  = g_dinv[node];
    float4 b = *(const float4*)&bias[c];
    float4 o;
    o.x = acc.x * d + b.x;
    o.y = acc.y * d + b.y;
    o.z = acc.z * d + b.z;
    o.w = acc.w * d + b.w;
    if (RELU) {
        o.x = fmaxf(o.x, 0.f);
        o.y = fmaxf(o.y, 0.f);
        o.z = fmaxf(o.z, 0.f);
        o.w = fmaxf(o.w, 0.f);
    }
    *(float4*)&OUT[node * DOUT + c] = o;
}

// ---------------------------------------------------------------------------
extern "C" void kernel_launch(void* const* d_in, const int* in_sizes, int n_in,
                              void* d_out, int out_size)
{
    const float* e_prev = (const float*)d_in[0];
    const int*   ei     = (const int*)d_in[1];   // int32 view; dtype detected
    const float* W1     = (const float*)d_in[2];
    const float* b1     = (const float*)d_in[3];
    const float* W2     = (const float*)d_in[4];
    const float* b2     = (const float*)d_in[5];
    float*       out    = (float*)d_out;

    int N = in_sizes[0] / 128;   // 50000
    int E = in_sizes[1] / 2;     // 800000 (element count, dtype-independent)

    // CSR build
    k_zero<<<(N + 255) / 256, 256>>>(N);
    k_detect<<<1, 256>>>(ei);
    k_hist<<<(E + 255) / 256, 256>>>(ei, E, N);
    k_part<<<NPART / 256, 256>>>(N);
    k_scanpart<<<1, 32>>>();
    k_offsets<<<NPART / 256, 256>>>(N, E);
    k_fill<<<(E + 255) / 256, 256>>>(ei, E, N);

    // Layer 1
    {
        int warps  = (N + 1) / 2;
        int blocks = (warps * 32 + 255) / 256;
        k_gemm<128, 0><<<blocks, 256>>>(e_prev, W1, N);
        constexpr int NPB = 256 / (128 / 4);      // 8 nodes per block
        k_agg<128, true, 0><<<(N + NPB - 1) / NPB, 256>>>(b1, nullptr, N);
    }

    // Layer 2
    {
        int warps  = (N + 1) / 2;
        int blocks = (warps * 32 + 255) / 256;
        k_gemm<64, 1><<<blocks, 256>>>(nullptr, W2, N);
        constexpr int NPB = 256 / (64 / 4);       // 16 nodes per block
        k_agg<64, false, 1><<<(N + NPB - 1) / NPB, 256>>>(b2, out, N);
    }
}